// round 17
// baseline (speedup 1.0000x reference)
#include <cuda_runtime.h>

#define BB 32
#define NN 128
#define HH 100
#define ROWS (BB*NN)    // 4096

// k_msg tile: 4 v-rows x one w-half(64), 128 threads, grid 2048.
#define WH 64
#define MSG_SMEM_BYTES (6400*4 + 256*16 + 256*4)   // 30720

// Scratch (static device allocations — allowed)
__device__ float g_hidden[ROWS*HH];
__device__ float g_hv[ROWS*HH];
__device__ float g_hw[ROWS*HH];
__device__ float g_msg [ROWS*HH];   // w in [0,64)
__device__ float g_msg2[ROWS*HH];   // w in [64,128)
__device__ float g_gterm[ROWS*HH];
__device__ int   g_nodemask[ROWS];
__device__ float g_maskf[ROWS*NN];  // edge mask as 0.0/1.0 float

typedef unsigned long long u64;

// ---------------------------------------------------------------------------
// init + node/edge masks + proj of pass 1. 8 rows/block, 128 thr, grid 512.
// Weight L2 traffic halved vs 4-row blocks.
// ---------------------------------------------------------------------------
__global__ void __launch_bounds__(128)
k_init_proj(const float* __restrict__ nodes, const float* __restrict__ edges,
            const float* __restrict__ Wv, const float* __restrict__ Ww) {
    __shared__ float4 sPa[HH];   // rows 0-3 transposed
    __shared__ float4 sPb[HH];   // rows 4-7 transposed
    int base = blockIdx.x * 8;
    int tid  = threadIdx.x;

    {   // masks: warp handles rows (warp) and (warp+4)
        int lane = tid & 31;
        #pragma unroll
        for (int rr = 0; rr < 2; rr++) {
            int r = (tid >> 5) + rr*4;
            const float4* e4 = (const float4*)edges + (size_t)(base + r) * NN;
            float s = 0.f;
            #pragma unroll
            for (int j = 0; j < 4; j++) {
                float4 e = e4[lane + 32*j];
                float sj = (e.x + e.y) + (e.z + e.w);
                g_maskf[(size_t)(base + r)*NN + lane + 32*j] =
                    (sj != 0.0f) ? 1.0f : 0.0f;
                s += sj;
            }
            #pragma unroll
            for (int off = 16; off > 0; off >>= 1)
                s += __shfl_xor_sync(0xffffffffu, s, off);
            if (lane == 0) g_nodemask[base + r] = (s != 0.0f) ? 1 : 0;
        }
    }

    float* sPaf = (float*)sPa;
    float* sPbf = (float*)sPb;
    for (int i = tid; i < 8*HH; i += 128) {
        int r = i / HH, k = i - r*HH;
        float x = nodes[(size_t)(base + r)*HH + k];
        g_hidden[(size_t)(base + r)*HH + k] = x;
        if (r < 4) sPaf[k*4 + r]       = x;
        else       sPbf[k*4 + (r - 4)] = x;
    }
    __syncthreads();

    if (tid < HH) {
        int h = tid;
        float v[8], u[8];
        #pragma unroll
        for (int r = 0; r < 8; r++) { v[r] = 0.f; u[r] = 0.f; }
        #pragma unroll 4
        for (int k = 0; k < HH; k++) {
            float4 xa = sPa[k], xb = sPb[k];
            float wv = Wv[k*HH + h];
            float ww = Ww[k*HH + h];
            v[0]=fmaf(xa.x,wv,v[0]); v[1]=fmaf(xa.y,wv,v[1]);
            v[2]=fmaf(xa.z,wv,v[2]); v[3]=fmaf(xa.w,wv,v[3]);
            v[4]=fmaf(xb.x,wv,v[4]); v[5]=fmaf(xb.y,wv,v[5]);
            v[6]=fmaf(xb.z,wv,v[6]); v[7]=fmaf(xb.w,wv,v[7]);
            u[0]=fmaf(xa.x,ww,u[0]); u[1]=fmaf(xa.y,ww,u[1]);
            u[2]=fmaf(xa.z,ww,u[2]); u[3]=fmaf(xa.w,ww,u[3]);
            u[4]=fmaf(xb.x,ww,u[4]); u[5]=fmaf(xb.y,ww,u[5]);
            u[6]=fmaf(xb.z,ww,u[6]); u[7]=fmaf(xb.w,ww,u[7]);
        }
        #pragma unroll
        for (int r = 0; r < 8; r++) {
            g_hv[(size_t)(base + r)*HH + h] = v[r];
            g_hw[(size_t)(base + r)*HH + h] = u[r];
        }
    }
}

// ---------------------------------------------------------------------------
// msg: partial[b,v,h] = sum_{w in half} [adj!=0]*relu(hv+hw+e.We)
// (unchanged from R15/R16 — issue 66%, near floor)
// ---------------------------------------------------------------------------
__global__ void __launch_bounds__(128, 7)
k_msg(const float* __restrict__ edges, const float* __restrict__ We) {
    extern __shared__ float smf[];
    float*  s_hw = smf;                     // [wl*100 + h]
    float4* s_e4 = (float4*)(smf + 6400);   // [v*64 + wl]
    float*  s_m  = smf + 6400 + 1024;       // [v*64 + wl]

    int bx   = blockIdx.x;
    int half = bx & 1;
    int v0   = ((bx >> 1) & 31) * 4;
    int b    = bx >> 6;
    int wofs = half * WH;
    int tid  = threadIdx.x;
    int bN   = b * NN;
    float* outp = half ? g_msg2 : g_msg;

    {
        u64* d = (u64*)s_hw;
        for (int i = tid; i < WH*50; i += 128) {
            int wl = i / 50, p = i - wl*50;
            d[i] = *(const u64*)(g_hw + (size_t)(bN + wofs + wl)*HH + 2*p);
        }
    }
    for (int i = tid; i < 4*WH; i += 128) {
        int v = i >> 6, wl = i & 63;
        size_t gofs = (size_t)(bN + v0 + v)*NN + wofs + wl;
        s_e4[i] = ((const float4*)edges)[gofs];
        s_m[i]  = g_maskf[gofs];
    }
    __syncthreads();

    int vloc = tid >> 5;
    int q    = tid & 31;
    if (q < 25) {
        int h0  = 4*q;
        int row = bN + v0 + vloc;
        float4 hv = *(const float4*)(g_hv + (size_t)row*HH + h0);
        float4 w0 = *(const float4*)(We + 0*HH + h0);
        float4 w1 = *(const float4*)(We + 1*HH + h0);
        float4 w2 = *(const float4*)(We + 2*HH + h0);
        float4 w3 = *(const float4*)(We + 3*HH + h0);

        const float4* ev  = s_e4 + vloc*WH;
        const float*  mv  = s_m  + vloc*WH;
        const float*  hwb = s_hw + h0;

        float a0 = 0.f, a1 = 0.f, a2 = 0.f, a3 = 0.f;
        #pragma unroll 2
        for (int wl = 0; wl < WH; wl++) {
            float4 e  = ev[wl];
            float4 hw = *(const float4*)(hwb + wl*100);
            float  m  = mv[wl];
            float p0 = hv.x + hw.x;
            float p1 = hv.y + hw.y;
            float p2 = hv.z + hw.z;
            float p3 = hv.w + hw.w;
            p0 = fmaf(e.x, w0.x, p0); p1 = fmaf(e.x, w0.y, p1);
            p2 = fmaf(e.x, w0.z, p2); p3 = fmaf(e.x, w0.w, p3);
            p0 = fmaf(e.y, w1.x, p0); p1 = fmaf(e.y, w1.y, p1);
            p2 = fmaf(e.y, w1.z, p2); p3 = fmaf(e.y, w1.w, p3);
            p0 = fmaf(e.z, w2.x, p0); p1 = fmaf(e.z, w2.y, p1);
            p2 = fmaf(e.z, w2.z, p2); p3 = fmaf(e.z, w2.w, p3);
            p0 = fmaf(e.w, w3.x, p0); p1 = fmaf(e.w, w3.y, p1);
            p2 = fmaf(e.w, w3.z, p2); p3 = fmaf(e.w, w3.w, p3);
            a0 = fmaf(fmaxf(p0, 0.f), m, a0);
            a1 = fmaf(fmaxf(p1, 0.f), m, a1);
            a2 = fmaf(fmaxf(p2, 0.f), m, a2);
            a3 = fmaf(fmaxf(p3, 0.f), m, a3);
        }
        *(float4*)(outp + (size_t)row*HH + h0) = make_float4(a0, a1, a2, a3);
    }
}

// ---------------------------------------------------------------------------
// update (masked tanh) fused with proj of the NEW hidden. 8 rows/block,
// 128 thr, grid 512. Weight L2 traffic halved. msg = g_msg + g_msg2.
// ---------------------------------------------------------------------------
__global__ void __launch_bounds__(128)
k_updproj(const float* __restrict__ Wu, const float* __restrict__ Wv,
          const float* __restrict__ Ww) {
    __shared__ float4 sUa[2*HH];     // [hidden;msg] rows 0-3
    __shared__ float4 sUb[2*HH];     // rows 4-7
    __shared__ float4 sPa[HH];       // new hidden rows 0-3
    __shared__ float4 sPb[HH];       // rows 4-7
    int base = blockIdx.x * 8;
    int tid  = threadIdx.x;
    float* sUaf = (float*)sUa;
    float* sUbf = (float*)sUb;
    float* sPaf = (float*)sPa;
    float* sPbf = (float*)sPb;

    for (int i = tid; i < 8*2*HH; i += 128) {
        int r = i / (2*HH), k = i - r*(2*HH);
        size_t idx = (size_t)(base + r)*HH;
        float x = (k < HH) ? g_hidden[idx + k]
                           : (g_msg[idx + (k - HH)] + g_msg2[idx + (k - HH)]);
        if (r < 4) sUaf[k*4 + r]       = x;
        else       sUbf[k*4 + (r - 4)] = x;
    }
    __syncthreads();

    if (tid < HH) {
        int h = tid;
        float a[8];
        #pragma unroll
        for (int r = 0; r < 8; r++) a[r] = 0.f;
        #pragma unroll 4
        for (int k = 0; k < 2*HH; k++) {
            float4 xa = sUa[k], xb = sUb[k];
            float w = Wu[k*HH + h];
            a[0]=fmaf(xa.x,w,a[0]); a[1]=fmaf(xa.y,w,a[1]);
            a[2]=fmaf(xa.z,w,a[2]); a[3]=fmaf(xa.w,w,a[3]);
            a[4]=fmaf(xb.x,w,a[4]); a[5]=fmaf(xb.y,w,a[5]);
            a[6]=fmaf(xb.z,w,a[6]); a[7]=fmaf(xb.w,w,a[7]);
        }
        float n[8];
        #pragma unroll
        for (int r = 0; r < 8; r++) {
            float oldv = (r < 4) ? sUaf[h*4 + r] : sUbf[h*4 + (r - 4)];
            n[r] = g_nodemask[base + r] ? tanhf(a[r]) : oldv;
            g_hidden[(size_t)(base + r)*HH + h] = n[r];
        }
        sPa[h] = make_float4(n[0], n[1], n[2], n[3]);
        sPb[h] = make_float4(n[4], n[5], n[6], n[7]);
    }
    __syncthreads();

    if (tid < HH) {
        int h = tid;
        float v[8], u[8];
        #pragma unroll
        for (int r = 0; r < 8; r++) { v[r] = 0.f; u[r] = 0.f; }
        #pragma unroll 4
        for (int k = 0; k < HH; k++) {
            float4 xa = sPa[k], xb = sPb[k];
            float wv = Wv[k*HH + h];
            float ww = Ww[k*HH + h];
            v[0]=fmaf(xa.x,wv,v[0]); v[1]=fmaf(xa.y,wv,v[1]);
            v[2]=fmaf(xa.z,wv,v[2]); v[3]=fmaf(xa.w,wv,v[3]);
            v[4]=fmaf(xb.x,wv,v[4]); v[5]=fmaf(xb.y,wv,v[5]);
            v[6]=fmaf(xb.z,wv,v[6]); v[7]=fmaf(xb.w,wv,v[7]);
            u[0]=fmaf(xa.x,ww,u[0]); u[1]=fmaf(xa.y,ww,u[1]);
            u[2]=fmaf(xa.z,ww,u[2]); u[3]=fmaf(xa.w,ww,u[3]);
            u[4]=fmaf(xb.x,ww,u[4]); u[5]=fmaf(xb.y,ww,u[5]);
            u[6]=fmaf(xb.z,ww,u[6]); u[7]=fmaf(xb.w,ww,u[7]);
        }
        #pragma unroll
        for (int r = 0; r < 8; r++) {
            g_hv[(size_t)(base + r)*HH + h] = v[r];
            g_hw[(size_t)(base + r)*HH + h] = u[r];
        }
    }
}

// ---------------------------------------------------------------------------
// final update fused with readout gterm. 8 rows/block, 128 thr, grid 512.
// ---------------------------------------------------------------------------
__global__ void __launch_bounds__(128)
k_updread(const float* __restrict__ nodes, const float* __restrict__ Wu,
          const float* __restrict__ Wr) {
    __shared__ float4 sUa[2*HH];
    __shared__ float4 sUb[2*HH];
    __shared__ float4 sRa[2*HH];     // [new_hidden; nodes] rows 0-3
    __shared__ float4 sRb[2*HH];     // rows 4-7
    int base = blockIdx.x * 8;
    int tid  = threadIdx.x;
    float* sUaf = (float*)sUa;
    float* sUbf = (float*)sUb;
    float* sRaf = (float*)sRa;
    float* sRbf = (float*)sRb;

    for (int i = tid; i < 8*2*HH; i += 128) {
        int r = i / (2*HH), k = i - r*(2*HH);
        size_t idx = (size_t)(base + r)*HH;
        float x = (k < HH) ? g_hidden[idx + k]
                           : (g_msg[idx + (k - HH)] + g_msg2[idx + (k - HH)]);
        if (r < 4) sUaf[k*4 + r]       = x;
        else       sUbf[k*4 + (r - 4)] = x;
    }
    for (int i = tid; i < 8*HH; i += 128) {
        int r = i / HH, k = i - r*HH;
        float x = nodes[(size_t)(base + r)*HH + k];
        if (r < 4) sRaf[(HH + k)*4 + r]       = x;
        else       sRbf[(HH + k)*4 + (r - 4)] = x;
    }
    __syncthreads();

    if (tid < HH) {
        int h = tid;
        float a[8];
        #pragma unroll
        for (int r = 0; r < 8; r++) a[r] = 0.f;
        #pragma unroll 4
        for (int k = 0; k < 2*HH; k++) {
            float4 xa = sUa[k], xb = sUb[k];
            float w = Wu[k*HH + h];
            a[0]=fmaf(xa.x,w,a[0]); a[1]=fmaf(xa.y,w,a[1]);
            a[2]=fmaf(xa.z,w,a[2]); a[3]=fmaf(xa.w,w,a[3]);
            a[4]=fmaf(xb.x,w,a[4]); a[5]=fmaf(xb.y,w,a[5]);
            a[6]=fmaf(xb.z,w,a[6]); a[7]=fmaf(xb.w,w,a[7]);
        }
        float n[8];
        #pragma unroll
        for (int r = 0; r < 8; r++) {
            float oldv = (r < 4) ? sUaf[h*4 + r] : sUbf[h*4 + (r - 4)];
            n[r] = g_nodemask[base + r] ? tanhf(a[r]) : oldv;
        }
        sRa[h] = make_float4(n[0], n[1], n[2], n[3]);
        sRb[h] = make_float4(n[4], n[5], n[6], n[7]);
    }
    __syncthreads();

    if (tid < HH) {
        int h = tid;
        float a[8];
        #pragma unroll
        for (int r = 0; r < 8; r++) a[r] = 0.f;
        #pragma unroll 4
        for (int k = 0; k < 2*HH; k++) {
            float4 xa = sRa[k], xb = sRb[k];
            float w = Wr[k*HH + h];
            a[0]=fmaf(xa.x,w,a[0]); a[1]=fmaf(xa.y,w,a[1]);
            a[2]=fmaf(xa.z,w,a[2]); a[3]=fmaf(xa.w,w,a[3]);
            a[4]=fmaf(xb.x,w,a[4]); a[5]=fmaf(xb.y,w,a[5]);
            a[6]=fmaf(xb.z,w,a[6]); a[7]=fmaf(xb.w,w,a[7]);
        }
        #pragma unroll
        for (int r = 0; r < 8; r++) {
            float m = g_nodemask[base + r] ? 1.f : 0.f;
            g_gterm[(size_t)(base + r)*HH + h] = fmaxf(a[r], 0.f) * m;
        }
    }
}

// ---------------------------------------------------------------------------
// reduce: out[b,h] = sum_v gterm[b,v,h]  (deterministic, no atomics)
// ---------------------------------------------------------------------------
__global__ void k_reduce(float* __restrict__ out) {
    int b   = blockIdx.x;
    int tid = threadIdx.x;           // 512
    int q   = tid >> 7;
    int h   = tid & 127;
    __shared__ float red[4][128];
    float acc = 0.f;
    if (h < HH) {
        int v0 = q * 32;
        #pragma unroll 4
        for (int v = v0; v < v0 + 32; v++)
            acc += g_gterm[(size_t)(b*NN + v)*HH + h];
    }
    red[q][h] = acc;
    __syncthreads();
    if (q == 0 && h < HH)
        out[b*HH + h] = (red[0][h] + red[1][h]) + (red[2][h] + red[3][h]);
}

extern "C" void kernel_launch(void* const* d_in, const int* in_sizes, int n_in,
                              void* d_out, int out_size) {
    const float* nodes = (const float*)d_in[0];
    const float* edges = (const float*)d_in[1];
    const float* Wv    = (const float*)d_in[2];
    const float* Ww    = (const float*)d_in[3];
    const float* We    = (const float*)d_in[4];
    const float* Wu    = (const float*)d_in[5];
    const float* Wr    = (const float*)d_in[6];
    float* out = (float*)d_out;

    cudaFuncSetAttribute(k_msg, cudaFuncAttributeMaxDynamicSharedMemorySize,
                         MSG_SMEM_BYTES);

    k_init_proj<<<ROWS/8, 128>>>(nodes, edges, Wv, Ww);
    for (int p = 0; p < 2; p++) {
        k_msg<<<2048, 128, MSG_SMEM_BYTES>>>(edges, We);
        k_updproj<<<ROWS/8, 128>>>(Wu, Wv, Ww);
    }
    k_msg<<<2048, 128, MSG_SMEM_BYTES>>>(edges, We);
    k_updread<<<ROWS/8, 128>>>(nodes, Wu, Wr);
    k_reduce<<<BB, 512>>>(out);
}